// round 14
// baseline (speedup 1.0000x reference)
#include <cuda_runtime.h>
#include <cuda_fp16.h>
#include <cstdint>

#define B_DIM    32
#define S_DIM    1024
#define DMODEL   1024
#define NDIS     14
#define ROWS_TOT (B_DIM * S_DIM)      /* 32768 */
#define KEXT     1056                 /* 1024 + 32 (P section padded) */

/* ------------- scratch (__device__ globals: no allocation allowed) -------- */
__device__ __half g_zb[(size_t)ROWS_TOT * DMODEL];   /* z in fp16      */
__device__ __half g_Bg[(size_t)1024 * KEXT];         /* [W1 ; MW2^T]   */
__device__ __half g_fmb[32 * 1024];                  /* flat_memory    */
__device__ __half g_Mp[1024 * 16];                   /* M_present^T    */
__device__ __half g_P[(size_t)ROWS_TOT * 32];        /* per-patch probs*/
__device__ int    g_mlc[B_DIM * NDIS];               /* max bits       */

/* ------------------------------ helpers ---------------------------------- */
__device__ __forceinline__ uint32_t smem_u32(const void* p) {
    return (uint32_t)__cvta_generic_to_shared(p);
}
__device__ __forceinline__ void cp16(uint32_t dst, const void* src) {
    asm volatile("cp.async.cg.shared.global [%0], [%1], 16;\n" :: "r"(dst), "l"(src));
}
__device__ __forceinline__ void cp_commit() { asm volatile("cp.async.commit_group;\n"); }
template <int N> __device__ __forceinline__ void cp_wait() {
    asm volatile("cp.async.wait_group %0;\n" :: "n"(N));
}
/* f16 inputs, f32 acc (scores kernel) */
__device__ __forceinline__ void mma_f32(float* d, const uint32_t* a, const uint32_t* b) {
    asm volatile(
        "mma.sync.aligned.m16n8k16.row.col.f32.f16.f16.f32 "
        "{%0,%1,%2,%3},{%4,%5,%6,%7},{%8,%9},{%0,%1,%2,%3};\n"
        : "+f"(d[0]), "+f"(d[1]), "+f"(d[2]), "+f"(d[3])
        : "r"(a[0]), "r"(a[1]), "r"(a[2]), "r"(a[3]), "r"(b[0]), "r"(b[1]));
}
/* f16 inputs, f16 acc (gate mainloop) */
__device__ __forceinline__ void mma_f16(uint32_t* d, const uint32_t* a, const uint32_t* b) {
    asm volatile(
        "mma.sync.aligned.m16n8k16.row.col.f16.f16.f16.f16 "
        "{%0,%1},{%2,%3,%4,%5},{%6,%7},{%0,%1};\n"
        : "+r"(d[0]), "+r"(d[1])
        : "r"(a[0]), "r"(a[1]), "r"(a[2]), "r"(a[3]), "r"(b[0]), "r"(b[1]));
}
__device__ __forceinline__ void ldsm4(uint32_t* r, uint32_t a) {
    asm volatile("ldmatrix.sync.aligned.m8n8.x4.shared.b16 {%0,%1,%2,%3}, [%4];"
                 : "=r"(r[0]), "=r"(r[1]), "=r"(r[2]), "=r"(r[3]) : "r"(a));
}
__device__ __forceinline__ float sigmoidf_(float x) { return 1.0f / (1.0f + __expf(-x)); }

/* --------------------------- prep: converts + zeros ----------------------- */
__global__ void k_prep(const float* __restrict__ dk, const float* __restrict__ gw) {
    const int T1 = 1024 * 1024;      /* Bg W1 part  */
    const int T2 = 32 * 1024;        /* fmb         */
    const int T3 = 1024 * 16;        /* Mp          */
    const int T4 = ROWS_TOT * 32;    /* zero g_P    */
    const int T5 = B_DIM * NDIS;     /* zero g_mlc  */
    const int TT = T1 + T2 + T3 + T4 + T5;
    for (int i = blockIdx.x * blockDim.x + threadIdx.x; i < TT; i += gridDim.x * blockDim.x) {
        if (i < T1) {
            int n = i >> 10, k = i & 1023;
            g_Bg[(size_t)n * KEXT + k] = __float2half_rn(gw[(size_t)n * 2048 + k]);
        } else if (i < T1 + T2) {
            int j = i - T1; int m = j >> 10, k = j & 1023;
            g_fmb[j] = (m < 28) ? __float2half_rn(dk[m * 1024 + k]) : __float2half_rn(0.f);
        } else if (i < T1 + T2 + T3) {
            int j = i - T1 - T2; int n = j >> 4, s = j & 15;
            g_Mp[j] = (s < NDIS) ? __float2half_rn(dk[(2 * s + 1) * 1024 + n])
                                 : __float2half_rn(0.f);
        } else if (i < T1 + T2 + T3 + T4) {
            g_P[i - T1 - T2 - T3] = __float2half_rn(0.f);
        } else {
            g_mlc[i - T1 - T2 - T3 - T4] = 0;
        }
    }
}

/* ------------- MW2[i][n] = sum_k M_present[i][k] * gate_w[n][1024+k] ------ */
__global__ void k_mw2(const float* __restrict__ dk, const float* __restrict__ gw) {
    int n = blockIdx.x;                 /* 0..1023 */
    int w = threadIdx.x >> 5;           /* 0..31 */
    int lane = threadIdx.x & 31;
    float v = 0.f;
    if (w < NDIS) {
        const float* m = dk + (2 * w + 1) * 1024;
        const float* g = gw + (size_t)n * 2048 + 1024;
        for (int k = lane; k < 1024; k += 32) v += m[k] * g[k];
        #pragma unroll
        for (int o = 16; o; o >>= 1) v += __shfl_xor_sync(0xffffffffu, v, o);
    }
    if (lane == 0) g_Bg[(size_t)n * KEXT + 1024 + w] = __float2half_rn(v);
}

/* ---------------- scores: P = sigmoid((s1-s0)/32), z->fp16, mlc max ------- */
/* R7 structure widened: 64 cols per iteration -> 16 barriers, MLP 8.        */
#define SC_ASTRIDE 72
#define SC_AST    (128 * SC_ASTRIDE)
#define FMB_STRIDE 1032
#define SC_SMEM ((32 * FMB_STRIDE + 2 * SC_AST) * 2)

__global__ __launch_bounds__(256) void k_scores(const float* __restrict__ z) {
    extern __shared__ __half sm[];
    __half* sFm = sm;                        /* [32][1032]    */
    __half* sA  = sm + 32 * FMB_STRIDE;      /* [2][128][72]  */
    __shared__ int sMax[16];

    int tid = threadIdx.x;
    for (int i = tid; i < 32 * 1024; i += 256) {
        int m = i >> 10, k = i & 1023;
        sFm[m * FMB_STRIDE + k] = g_fmb[i];
    }
    if (tid < 16) sMax[tid] = 0;

    int rowbase = blockIdx.x * 128;
    int r = tid >> 1, half_ = tid & 1;       /* thread covers 32 cols */
    const float* gz = z + (size_t)(rowbase + r) * 1024 + half_ * 32;

    float4 f[8];
    #pragma unroll
    for (int j = 0; j < 8; j++) f[j] = *(const float4*)(gz + j * 4);

    float acc[4][4];
    #pragma unroll
    for (int a = 0; a < 4; a++)
        #pragma unroll
        for (int b = 0; b < 4; b++) acc[a][b] = 0.f;

    int wid = tid >> 5, lane = tid & 31, gid = lane >> 2, tig = lane & 3;

    uint4* sAu0 = (uint4*)(sA + r * SC_ASTRIDE + half_ * 32);
    uint4* sAu1 = (uint4*)(sA + SC_AST + r * SC_ASTRIDE + half_ * 32);
    uint4* gzb  = (uint4*)(g_zb + (size_t)(rowbase + r) * 1024 + half_ * 32);

    for (int c = 0; c < 16; c++) {           /* 16 iterations of 64 cols */
        uint4 q[4];
        #pragma unroll
        for (int j = 0; j < 4; j++) {
            __half2 h0 = __floats2half2_rn(f[2 * j].x, f[2 * j].y);
            __half2 h1 = __floats2half2_rn(f[2 * j].z, f[2 * j].w);
            __half2 h2 = __floats2half2_rn(f[2 * j + 1].x, f[2 * j + 1].y);
            __half2 h3 = __floats2half2_rn(f[2 * j + 1].z, f[2 * j + 1].w);
            q[j].x = *(uint32_t*)&h0; q[j].y = *(uint32_t*)&h1;
            q[j].z = *(uint32_t*)&h2; q[j].w = *(uint32_t*)&h3;
        }
        uint4* dst = (c & 1) ? sAu1 : sAu0;
        #pragma unroll
        for (int j = 0; j < 4; j++) {
            dst[j] = q[j];
            gzb[c * 8 + j] = q[j];
        }

        __syncthreads();

        if (c + 1 < 16) {
            const float* gn = gz + (c + 1) * 64;
            #pragma unroll
            for (int j = 0; j < 8; j++) f[j] = *(const float4*)(gn + j * 4);
        }

        const __half* sAb = sA + (c & 1) * SC_AST;
        #pragma unroll
        for (int kk = 0; kk < 4; kk++) {
            uint32_t a[4];
            const __half* ap = sAb + (wid * 16 + gid) * SC_ASTRIDE + kk * 16 + 2 * tig;
            a[0] = *(const uint32_t*)ap;
            a[1] = *(const uint32_t*)(ap + 8 * SC_ASTRIDE);
            a[2] = *(const uint32_t*)(ap + 8);
            a[3] = *(const uint32_t*)(ap + 8 * SC_ASTRIDE + 8);
            #pragma unroll
            for (int nt = 0; nt < 4; nt++) {
                uint32_t b[2];
                const __half* bp = sFm + (nt * 8 + gid) * FMB_STRIDE + c * 64 + kk * 16 + 2 * tig;
                b[0] = *(const uint32_t*)bp;
                b[1] = *(const uint32_t*)(bp + 8);
                mma_f32(acc[nt], a, b);
            }
        }
    }

    int row0 = rowbase + wid * 16 + gid;
    const float inv = 1.0f / 32.0f;   /* 1/sqrt(1024) */
    #pragma unroll
    for (int nt = 0; nt < 4; nt++) {
        int d = nt * 4 + tig;
        float p0 = 0.f, p1 = 0.f;
        if (d < NDIS) {
            p0 = sigmoidf_((acc[nt][1] - acc[nt][0]) * inv);
            p1 = sigmoidf_((acc[nt][3] - acc[nt][2]) * inv);
        }
        g_P[(size_t)row0 * 32 + d]       = __float2half_rn(p0);
        g_P[(size_t)(row0 + 8) * 32 + d] = __float2half_rn(p1);
        if (d < NDIS) {
            atomicMax(&sMax[d], __float_as_int(p0));
            atomicMax(&sMax[d], __float_as_int(p1));
        }
    }
    __syncthreads();
    if (tid < NDIS) {
        int b = rowbase >> 10;
        atomicMax(&g_mlc[b * NDIS + tid], sMax[tid]);
    }
}

/* -------- main fused GEMM: [z|P] @ [W1;MW2], + R mma + sigmoid + out ------ */
/* 512 threads, 16 warps (4x4), warp tile 32x32, 4-stage cp.async ring.      */
#define G_STRIDE 40
#define ST_ELE   (128 * G_STRIDE)           /* elems per stage per matrix */
#define NSTAGE   4
#define GATE_SMEM ((NSTAGE * 2 * ST_ELE + 128 * 16) * 2)   /* 84 KB */

__global__ __launch_bounds__(512, 2) void k_gate(const float* __restrict__ z,
                                                 const float* __restrict__ gb,
                                                 float* __restrict__ out) {
    extern __shared__ __half sg[];
    __half* sA  = sg;                         /* [4][128*40] */
    __half* sB  = sg + NSTAGE * ST_ELE;       /* [4][128*40] */
    __half* sMp = sg + 2 * NSTAGE * ST_ELE;   /* [128][16]   */

    int bn = blockIdx.x & 7, bm = blockIdx.x >> 3;
    int rowbase = bm * 128, colbase = bn * 128;
    int tid = threadIdx.x, wid = tid >> 5, lane = tid & 31;
    int gid = lane >> 2, tig = lane & 3;
    int wm = wid & 3, wn = wid >> 2;          /* 4x4 warp grid */

    uint32_t acc[2][4][2];                    /* f16x2 accumulators, 32x32 tile */
    #pragma unroll
    for (int a = 0; a < 2; a++)
        #pragma unroll
        for (int b = 0; b < 4; b++) { acc[a][b][0] = 0u; acc[a][b][1] = 0u; }

    int lr = tid >> 2, lj = tid & 3;          /* row 0..127, one 16B per thread */

    #define LOAD_A(c, s) do {                                                      \
        const __half* _s;                                                          \
        if ((c) < 32) _s = g_zb + (size_t)(rowbase + lr) * 1024 + (c) * 32 + lj * 8;\
        else          _s = g_P  + (size_t)(rowbase + lr) * 32 + lj * 8;            \
        cp16(smem_u32(&sA[(s) * ST_ELE + lr * G_STRIDE + lj * 8]), _s);            \
    } while (0)
    #define LOAD_B(c, s) do {                                                      \
        const __half* _s = g_Bg + (size_t)(colbase + lr) * KEXT + (c) * 32 + lj * 8; \
        cp16(smem_u32(&sB[(s) * ST_ELE + lr * G_STRIDE + lj * 8]), _s);            \
    } while (0)

    LOAD_A(0, 0); LOAD_B(0, 0); cp_commit();
    LOAD_A(1, 1); LOAD_B(1, 1); cp_commit();
    LOAD_A(2, 2); LOAD_B(2, 2); cp_commit();

    /* per-lane ldmatrix base addresses */
    int l = lane;
    int rAm = (l & 7) + ((l >> 3) & 1) * 8;
    int kA8 = (l >> 4) * 8;
    int rBn = (l & 7) + ((l >> 4) & 1) * 8;
    int kB8 = ((l >> 3) & 1) * 8;
    uint32_t baseA = smem_u32(sA) + (uint32_t)(((wm * 32 + rAm) * G_STRIDE + kA8) * 2);
    uint32_t baseB = smem_u32(sB) + (uint32_t)(((wn * 32 + rBn) * G_STRIDE + kB8) * 2);

    for (int c = 0; c < 33; c++) {
        int s = c & 3;
        if (c <= 30)      cp_wait<2>();
        else if (c == 31) cp_wait<1>();
        else              cp_wait<0>();
        __syncthreads();
        if (c + 3 < 33) { LOAD_A(c + 3, (c + 3) & 3); LOAD_B(c + 3, (c + 3) & 3); cp_commit(); }

        uint32_t sOff = (uint32_t)(s * ST_ELE * 2);
        #pragma unroll
        for (int kk = 0; kk < 2; kk++) {
            uint32_t a[2][4], b[4][2];
            ldsm4(a[0], baseA + sOff + kk * 32);
            ldsm4(a[1], baseA + sOff + kk * 32 + 16 * G_STRIDE * 2);
            #pragma unroll
            for (int p = 0; p < 2; p++) {
                uint32_t t[4];
                ldsm4(t, baseB + sOff + kk * 32 + (uint32_t)(p * 16 * G_STRIDE * 2));
                b[2 * p][0] = t[0]; b[2 * p][1] = t[1];
                b[2 * p + 1][0] = t[2]; b[2 * p + 1][1] = t[3];
            }
            #pragma unroll
            for (int mt = 0; mt < 2; mt++)
                #pragma unroll
                for (int nt = 0; nt < 4; nt++)
                    mma_f16(acc[mt][nt], a[mt], b[nt]);
        }
    }
    __syncthreads();

    /* epilogue: P chunk (c=32) lives in slot 32&3 = 0 */
    for (int i = tid; i < 128 * 16; i += 512)
        sMp[i] = g_Mp[(size_t)(colbase + (i >> 4)) * 16 + (i & 15)];
    __syncthreads();

    uint32_t aP[2][4];
    #pragma unroll
    for (int mt = 0; mt < 2; mt++) {
        const __half* ap = &sA[(wm * 32 + mt * 16 + gid) * G_STRIDE + 2 * tig];
        aP[mt][0] = *(const uint32_t*)ap;
        aP[mt][1] = *(const uint32_t*)(ap + 8 * G_STRIDE);
        aP[mt][2] = *(const uint32_t*)(ap + 8);
        aP[mt][3] = *(const uint32_t*)(ap + 8 * G_STRIDE + 8);
    }

    #pragma unroll
    for (int nt = 0; nt < 4; nt++) {
        uint32_t racc[2][2];
        racc[0][0] = racc[0][1] = racc[1][0] = racc[1][1] = 0u;
        uint32_t b[2];
        const __half* bp = &sMp[(wn * 32 + nt * 8 + gid) * 16 + 2 * tig];
        b[0] = *(const uint32_t*)bp;
        b[1] = *(const uint32_t*)(bp + 8);
        mma_f16(racc[0], aP[0], b);
        mma_f16(racc[1], aP[1], b);

        int col = colbase + wn * 32 + nt * 8 + 2 * tig;
        float b0 = gb[col], b1 = gb[col + 1];
        #pragma unroll
        for (int mt = 0; mt < 2; mt++) {
            int row = rowbase + wm * 32 + mt * 16 + gid;
            #pragma unroll
            for (int h = 0; h < 2; h++) {
                int rr = row + h * 8;
                float2 dh = __half22float2(*(__half2*)&acc[mt][nt][h]);
                float2 rh = __half22float2(*(__half2*)&racc[mt][h]);
                float g0 = sigmoidf_(dh.x + b0);
                float g1 = sigmoidf_(dh.y + b1);
                const float2 zz = *(const float2*)(z + (size_t)rr * 1024 + col);
                float2 o;
                o.x = zz.x + g0 * rh.x;
                o.y = zz.y + g1 * rh.y;
                *(float2*)(out + (size_t)rr * 1024 + col) = o;
            }
        }
    }
    #undef LOAD_A
    #undef LOAD_B
}

/* ---------------- write mlc_probs tail of the output ---------------------- */
__global__ void k_finish(float* __restrict__ out, int tail) {
    int i = threadIdx.x + blockIdx.x * blockDim.x;
    if (i < B_DIM * NDIS) out[tail + i] = __int_as_float(g_mlc[i]);
}

/* -------------------------------- launch ---------------------------------- */
extern "C" void kernel_launch(void* const* d_in, const int* in_sizes, int n_in,
                              void* d_out, int out_size) {
    const float* z  = (const float*)d_in[0];   /* (32,1024,1024)  */
    const float* dk = (const float*)d_in[1];   /* (14,2,1024)     */
    const float* gw = (const float*)d_in[2];   /* (1024,2048)     */
    const float* gb = (const float*)d_in[3];   /* (1024,)         */
    float* out = (float*)d_out;

    cudaFuncSetAttribute(k_scores, cudaFuncAttributeMaxDynamicSharedMemorySize, SC_SMEM);
    cudaFuncSetAttribute(k_gate, cudaFuncAttributeMaxDynamicSharedMemorySize, GATE_SMEM);

    k_prep<<<512, 256>>>(dk, gw);
    k_mw2<<<1024, 1024>>>(dk, gw);
    k_scores<<<ROWS_TOT / 128, 256, SC_SMEM>>>(z);
    k_gate<<<(ROWS_TOT / 128) * 8, 512, GATE_SMEM>>>(z, gb, out);
    k_finish<<<1, 448>>>(out, out_size - B_DIM * NDIS);
}

// round 15
// speedup vs baseline: 1.0779x; 1.0779x over previous
#include <cuda_runtime.h>
#include <cuda_fp16.h>
#include <cstdint>

#define B_DIM    32
#define S_DIM    1024
#define DMODEL   1024
#define NDIS     14
#define ROWS_TOT (B_DIM * S_DIM)      /* 32768 */
#define KEXT     1056                 /* 1024 + 32 (P section padded) */

/* ------------- scratch (__device__ globals: no allocation allowed) -------- */
__device__ __half g_zb[(size_t)ROWS_TOT * DMODEL];   /* z in fp16      */
__device__ __half g_Bg[(size_t)1024 * KEXT];         /* [W1 ; MW2^T]   */
__device__ __half g_fmb[32 * 1024];                  /* flat_memory    */
__device__ __half g_Mp[1024 * 16];                   /* M_present^T    */
__device__ __half g_P[(size_t)ROWS_TOT * 32];        /* per-patch probs*/
__device__ int    g_mlc[B_DIM * NDIS];               /* max bits       */

/* ------------------------------ helpers ---------------------------------- */
__device__ __forceinline__ uint32_t smem_u32(const void* p) {
    return (uint32_t)__cvta_generic_to_shared(p);
}
__device__ __forceinline__ void cp16(uint32_t dst, const void* src) {
    asm volatile("cp.async.cg.shared.global [%0], [%1], 16;\n" :: "r"(dst), "l"(src));
}
__device__ __forceinline__ void cp_commit() { asm volatile("cp.async.commit_group;\n"); }
template <int N> __device__ __forceinline__ void cp_wait() {
    asm volatile("cp.async.wait_group %0;\n" :: "n"(N));
}
/* f16 inputs, f32 acc (scores kernel) */
__device__ __forceinline__ void mma_f32(float* d, const uint32_t* a, const uint32_t* b) {
    asm volatile(
        "mma.sync.aligned.m16n8k16.row.col.f32.f16.f16.f32 "
        "{%0,%1,%2,%3},{%4,%5,%6,%7},{%8,%9},{%0,%1,%2,%3};\n"
        : "+f"(d[0]), "+f"(d[1]), "+f"(d[2]), "+f"(d[3])
        : "r"(a[0]), "r"(a[1]), "r"(a[2]), "r"(a[3]), "r"(b[0]), "r"(b[1]));
}
/* f16 inputs, f16 acc (gate mainloop) */
__device__ __forceinline__ void mma_f16(uint32_t* d, const uint32_t* a, const uint32_t* b) {
    asm volatile(
        "mma.sync.aligned.m16n8k16.row.col.f16.f16.f16.f16 "
        "{%0,%1},{%2,%3,%4,%5},{%6,%7},{%0,%1};\n"
        : "+r"(d[0]), "+r"(d[1])
        : "r"(a[0]), "r"(a[1]), "r"(a[2]), "r"(a[3]), "r"(b[0]), "r"(b[1]));
}
__device__ __forceinline__ void ldsm4(uint32_t* r, uint32_t a) {
    asm volatile("ldmatrix.sync.aligned.m8n8.x4.shared.b16 {%0,%1,%2,%3}, [%4];"
                 : "=r"(r[0]), "=r"(r[1]), "=r"(r[2]), "=r"(r[3]) : "r"(a));
}
__device__ __forceinline__ float sigmoidf_(float x) { return 1.0f / (1.0f + __expf(-x)); }

/* ------------- prep0: fmb + Mp + P-zero + mlc-zero (main stream) ---------- */
__global__ void k_prep0(const float* __restrict__ dk) {
    const int T2 = 32 * 1024;        /* fmb      */
    const int T3 = 1024 * 16;        /* Mp       */
    const int T4 = ROWS_TOT * 32;    /* zero g_P */
    const int T5 = B_DIM * NDIS;     /* zero mlc */
    const int TT = T2 + T3 + T4 + T5;
    for (int i = blockIdx.x * blockDim.x + threadIdx.x; i < TT; i += gridDim.x * blockDim.x) {
        if (i < T2) {
            int m = i >> 10, k = i & 1023;
            g_fmb[i] = (m < 28) ? __float2half_rn(dk[m * 1024 + k]) : __float2half_rn(0.f);
        } else if (i < T2 + T3) {
            int j = i - T2; int n = j >> 4, s = j & 15;
            g_Mp[j] = (s < NDIS) ? __float2half_rn(dk[(2 * s + 1) * 1024 + n])
                                 : __float2half_rn(0.f);
        } else if (i < T2 + T3 + T4) {
            g_P[i - T2 - T3] = __float2half_rn(0.f);
        } else {
            g_mlc[i - T2 - T3 - T4] = 0;
        }
    }
}

/* ------------- prepBg: W1 fp32 -> fp16 into g_Bg (side stream) ------------ */
__global__ void k_prepBg(const float* __restrict__ gw) {
    for (int i = blockIdx.x * blockDim.x + threadIdx.x; i < 1024 * 1024;
         i += gridDim.x * blockDim.x) {
        int n = i >> 10, k = i & 1023;
        g_Bg[(size_t)n * KEXT + k] = __float2half_rn(gw[(size_t)n * 2048 + k]);
    }
}

/* ------------- MW2[i][n] = sum_k M_present[i][k] * gate_w[n][1024+k] ------ */
__global__ void k_mw2(const float* __restrict__ dk, const float* __restrict__ gw) {
    int n = blockIdx.x;                 /* 0..1023 */
    int w = threadIdx.x >> 5;           /* 0..31 */
    int lane = threadIdx.x & 31;
    float v = 0.f;
    if (w < NDIS) {
        const float* m = dk + (2 * w + 1) * 1024;
        const float* g = gw + (size_t)n * 2048 + 1024;
        for (int k = lane; k < 1024; k += 32) v += m[k] * g[k];
        #pragma unroll
        for (int o = 16; o; o >>= 1) v += __shfl_xor_sync(0xffffffffu, v, o);
    }
    if (lane == 0) g_Bg[(size_t)n * KEXT + 1024 + w] = __float2half_rn(v);
}

/* ---------------- scores: P = sigmoid((s1-s0)/32), z->fp16, mlc max ------- */
/* Double-buffered sA, ONE __syncthreads per chunk, 128-bit stores.           */
#define SC_ASTRIDE 40
#define SC_AST    (128 * SC_ASTRIDE)
#define FMB_STRIDE 1032
#define SC_SMEM ((32 * FMB_STRIDE + 2 * SC_AST) * 2)

__global__ __launch_bounds__(256) void k_scores(const float* __restrict__ z) {
    extern __shared__ __half sm[];
    __half* sFm = sm;                        /* [32][1032]    */
    __half* sA  = sm + 32 * FMB_STRIDE;      /* [2][128][40]  */
    __shared__ int sMax[16];

    int tid = threadIdx.x;
    for (int i = tid; i < 32 * 1024; i += 256) {
        int m = i >> 10, k = i & 1023;
        sFm[m * FMB_STRIDE + k] = g_fmb[i];
    }
    if (tid < 16) sMax[tid] = 0;

    int rowbase = blockIdx.x * 128;
    int r = tid >> 1, half_ = tid & 1;
    const float* gz = z + (size_t)(rowbase + r) * 1024 + half_ * 16;

    float4 f[4];
    #pragma unroll
    for (int j = 0; j < 4; j++) f[j] = *(const float4*)(gz + j * 4);

    float acc[4][4];
    #pragma unroll
    for (int a = 0; a < 4; a++)
        #pragma unroll
        for (int b = 0; b < 4; b++) acc[a][b] = 0.f;

    int wid = tid >> 5, lane = tid & 31, gid = lane >> 2, tig = lane & 3;

    uint4* sAu0 = (uint4*)(sA + r * SC_ASTRIDE + half_ * 16);
    uint4* sAu1 = (uint4*)(sA + SC_AST + r * SC_ASTRIDE + half_ * 16);
    uint4* gzb  = (uint4*)(g_zb + (size_t)(rowbase + r) * 1024 + half_ * 16);

    for (int c = 0; c < 32; c++) {
        uint4 q0, q1;
        {
            __half2 h0 = __floats2half2_rn(f[0].x, f[0].y);
            __half2 h1 = __floats2half2_rn(f[0].z, f[0].w);
            __half2 h2 = __floats2half2_rn(f[1].x, f[1].y);
            __half2 h3 = __floats2half2_rn(f[1].z, f[1].w);
            q0.x = *(uint32_t*)&h0; q0.y = *(uint32_t*)&h1;
            q0.z = *(uint32_t*)&h2; q0.w = *(uint32_t*)&h3;
            __half2 h4 = __floats2half2_rn(f[2].x, f[2].y);
            __half2 h5 = __floats2half2_rn(f[2].z, f[2].w);
            __half2 h6 = __floats2half2_rn(f[3].x, f[3].y);
            __half2 h7 = __floats2half2_rn(f[3].z, f[3].w);
            q1.x = *(uint32_t*)&h4; q1.y = *(uint32_t*)&h5;
            q1.z = *(uint32_t*)&h6; q1.w = *(uint32_t*)&h7;
        }
        uint4* dst = (c & 1) ? sAu1 : sAu0;
        dst[0] = q0;  dst[1] = q1;
        gzb[c * 4 + 0] = q0;  gzb[c * 4 + 1] = q1;

        __syncthreads();

        if (c + 1 < 32) {
            const float* gn = gz + (c + 1) * 32;
            #pragma unroll
            for (int j = 0; j < 4; j++) f[j] = *(const float4*)(gn + j * 4);
        }

        const __half* sAb = sA + (c & 1) * SC_AST;
        #pragma unroll
        for (int kk = 0; kk < 2; kk++) {
            uint32_t a[4];
            const __half* ap = sAb + (wid * 16 + gid) * SC_ASTRIDE + kk * 16 + 2 * tig;
            a[0] = *(const uint32_t*)ap;
            a[1] = *(const uint32_t*)(ap + 8 * SC_ASTRIDE);
            a[2] = *(const uint32_t*)(ap + 8);
            a[3] = *(const uint32_t*)(ap + 8 * SC_ASTRIDE + 8);
            #pragma unroll
            for (int nt = 0; nt < 4; nt++) {
                uint32_t b[2];
                const __half* bp = sFm + (nt * 8 + gid) * FMB_STRIDE + c * 32 + kk * 16 + 2 * tig;
                b[0] = *(const uint32_t*)bp;
                b[1] = *(const uint32_t*)(bp + 8);
                mma_f32(acc[nt], a, b);
            }
        }
    }

    int row0 = rowbase + wid * 16 + gid;
    const float inv = 1.0f / 32.0f;   /* 1/sqrt(1024) */
    #pragma unroll
    for (int nt = 0; nt < 4; nt++) {
        int d = nt * 4 + tig;
        float p0 = 0.f, p1 = 0.f;
        if (d < NDIS) {
            p0 = sigmoidf_((acc[nt][1] - acc[nt][0]) * inv);
            p1 = sigmoidf_((acc[nt][3] - acc[nt][2]) * inv);
        }
        g_P[(size_t)row0 * 32 + d]       = __float2half_rn(p0);
        g_P[(size_t)(row0 + 8) * 32 + d] = __float2half_rn(p1);
        if (d < NDIS) {
            atomicMax(&sMax[d], __float_as_int(p0));
            atomicMax(&sMax[d], __float_as_int(p1));
        }
    }
    __syncthreads();
    if (tid < NDIS) {
        int b = rowbase >> 10;
        atomicMax(&g_mlc[b * NDIS + tid], sMax[tid]);
    }
}

/* -------- main fused GEMM: [z|P] @ [W1;MW2], + R mma + sigmoid + out ------ */
/* 512 threads, 16 warps (4x4), warp tile 32x32, 4-stage cp.async ring.      */
#define G_STRIDE 40
#define ST_ELE   (128 * G_STRIDE)           /* elems per stage per matrix */
#define NSTAGE   4
#define GATE_SMEM ((NSTAGE * 2 * ST_ELE + 128 * 16) * 2)   /* 84 KB */

__global__ __launch_bounds__(512, 2) void k_gate(const float* __restrict__ z,
                                                 const float* __restrict__ gb,
                                                 float* __restrict__ out) {
    extern __shared__ __half sg[];
    __half* sA  = sg;                         /* [4][128*40] */
    __half* sB  = sg + NSTAGE * ST_ELE;       /* [4][128*40] */
    __half* sMp = sg + 2 * NSTAGE * ST_ELE;   /* [128][16]   */

    int bn = blockIdx.x & 7, bm = blockIdx.x >> 3;
    int rowbase = bm * 128, colbase = bn * 128;
    int tid = threadIdx.x, wid = tid >> 5, lane = tid & 31;
    int gid = lane >> 2, tig = lane & 3;
    int wm = wid & 3, wn = wid >> 2;          /* 4x4 warp grid */

    uint32_t acc[2][4][2];                    /* f16x2 accumulators, 32x32 tile */
    #pragma unroll
    for (int a = 0; a < 2; a++)
        #pragma unroll
        for (int b = 0; b < 4; b++) { acc[a][b][0] = 0u; acc[a][b][1] = 0u; }

    int lr = tid >> 2, lj = tid & 3;          /* row 0..127, one 16B per thread */

    #define LOAD_A(c, s) do {                                                      \
        const __half* _s;                                                          \
        if ((c) < 32) _s = g_zb + (size_t)(rowbase + lr) * 1024 + (c) * 32 + lj * 8;\
        else          _s = g_P  + (size_t)(rowbase + lr) * 32 + lj * 8;            \
        cp16(smem_u32(&sA[(s) * ST_ELE + lr * G_STRIDE + lj * 8]), _s);            \
    } while (0)
    #define LOAD_B(c, s) do {                                                      \
        const __half* _s = g_Bg + (size_t)(colbase + lr) * KEXT + (c) * 32 + lj * 8; \
        cp16(smem_u32(&sB[(s) * ST_ELE + lr * G_STRIDE + lj * 8]), _s);            \
    } while (0)

    LOAD_A(0, 0); LOAD_B(0, 0); cp_commit();
    LOAD_A(1, 1); LOAD_B(1, 1); cp_commit();
    LOAD_A(2, 2); LOAD_B(2, 2); cp_commit();

    /* per-lane ldmatrix base addresses */
    int l = lane;
    int rAm = (l & 7) + ((l >> 3) & 1) * 8;
    int kA8 = (l >> 4) * 8;
    int rBn = (l & 7) + ((l >> 4) & 1) * 8;
    int kB8 = ((l >> 3) & 1) * 8;
    uint32_t baseA = smem_u32(sA) + (uint32_t)(((wm * 32 + rAm) * G_STRIDE + kA8) * 2);
    uint32_t baseB = smem_u32(sB) + (uint32_t)(((wn * 32 + rBn) * G_STRIDE + kB8) * 2);

    for (int c = 0; c < 33; c++) {
        int s = c & 3;
        if (c <= 30)      cp_wait<2>();
        else if (c == 31) cp_wait<1>();
        else              cp_wait<0>();
        __syncthreads();
        if (c + 3 < 33) { LOAD_A(c + 3, (c + 3) & 3); LOAD_B(c + 3, (c + 3) & 3); cp_commit(); }

        uint32_t sOff = (uint32_t)(s * ST_ELE * 2);
        #pragma unroll
        for (int kk = 0; kk < 2; kk++) {
            uint32_t a[2][4], b[4][2];
            ldsm4(a[0], baseA + sOff + kk * 32);
            ldsm4(a[1], baseA + sOff + kk * 32 + 16 * G_STRIDE * 2);
            #pragma unroll
            for (int p = 0; p < 2; p++) {
                uint32_t t[4];
                ldsm4(t, baseB + sOff + kk * 32 + (uint32_t)(p * 16 * G_STRIDE * 2));
                b[2 * p][0] = t[0]; b[2 * p][1] = t[1];
                b[2 * p + 1][0] = t[2]; b[2 * p + 1][1] = t[3];
            }
            #pragma unroll
            for (int mt = 0; mt < 2; mt++)
                #pragma unroll
                for (int nt = 0; nt < 4; nt++)
                    mma_f16(acc[mt][nt], a[mt], b[nt]);
        }
    }
    __syncthreads();

    /* epilogue: P chunk (c=32) lives in slot 32&3 = 0 */
    for (int i = tid; i < 128 * 16; i += 512)
        sMp[i] = g_Mp[(size_t)(colbase + (i >> 4)) * 16 + (i & 15)];
    __syncthreads();

    uint32_t aP[2][4];
    #pragma unroll
    for (int mt = 0; mt < 2; mt++) {
        const __half* ap = &sA[(wm * 32 + mt * 16 + gid) * G_STRIDE + 2 * tig];
        aP[mt][0] = *(const uint32_t*)ap;
        aP[mt][1] = *(const uint32_t*)(ap + 8 * G_STRIDE);
        aP[mt][2] = *(const uint32_t*)(ap + 8);
        aP[mt][3] = *(const uint32_t*)(ap + 8 * G_STRIDE + 8);
    }

    #pragma unroll
    for (int nt = 0; nt < 4; nt++) {
        uint32_t racc[2][2];
        racc[0][0] = racc[0][1] = racc[1][0] = racc[1][1] = 0u;
        uint32_t b[2];
        const __half* bp = &sMp[(wn * 32 + nt * 8 + gid) * 16 + 2 * tig];
        b[0] = *(const uint32_t*)bp;
        b[1] = *(const uint32_t*)(bp + 8);
        mma_f16(racc[0], aP[0], b);
        mma_f16(racc[1], aP[1], b);

        int col = colbase + wn * 32 + nt * 8 + 2 * tig;
        float b0 = gb[col], b1 = gb[col + 1];
        #pragma unroll
        for (int mt = 0; mt < 2; mt++) {
            int row = rowbase + wm * 32 + mt * 16 + gid;
            #pragma unroll
            for (int h = 0; h < 2; h++) {
                int rr = row + h * 8;
                float2 dh = __half22float2(*(__half2*)&acc[mt][nt][h]);
                float2 rh = __half22float2(*(__half2*)&racc[mt][h]);
                float g0 = sigmoidf_(dh.x + b0);
                float g1 = sigmoidf_(dh.y + b1);
                const float2 zz = *(const float2*)(z + (size_t)rr * 1024 + col);
                float2 o;
                o.x = zz.x + g0 * rh.x;
                o.y = zz.y + g1 * rh.y;
                *(float2*)(out + (size_t)rr * 1024 + col) = o;
            }
        }
    }
    #undef LOAD_A
    #undef LOAD_B
}

/* ---------------- write mlc_probs tail of the output ---------------------- */
__global__ void k_finish(float* __restrict__ out, int tail) {
    int i = threadIdx.x + blockIdx.x * blockDim.x;
    if (i < B_DIM * NDIS) out[tail + i] = __int_as_float(g_mlc[i]);
}

/* -------------------------------- launch ---------------------------------- */
extern "C" void kernel_launch(void* const* d_in, const int* in_sizes, int n_in,
                              void* d_out, int out_size) {
    const float* z  = (const float*)d_in[0];   /* (32,1024,1024)  */
    const float* dk = (const float*)d_in[1];   /* (14,2,1024)     */
    const float* gw = (const float*)d_in[2];   /* (1024,2048)     */
    const float* gb = (const float*)d_in[3];   /* (1024,)         */
    float* out = (float*)d_out;

    cudaFuncSetAttribute(k_scores, cudaFuncAttributeMaxDynamicSharedMemorySize, SC_SMEM);
    cudaFuncSetAttribute(k_gate, cudaFuncAttributeMaxDynamicSharedMemorySize, GATE_SMEM);

    /* Fresh stream/events each call (never destroyed — kernel_launch runs only
       a handful of times; handles are host-side, no device allocation).
       Cross-stream fork/join via events is graph-capturable. */
    cudaStream_t s2;
    cudaEvent_t evFork, evJoin;
    cudaStreamCreateWithFlags(&s2, cudaStreamNonBlocking);
    cudaEventCreateWithFlags(&evFork, cudaEventDisableTiming);
    cudaEventCreateWithFlags(&evJoin, cudaEventDisableTiming);

    /* main stream: small prep needed by k_scores */
    k_prep0<<<256, 256>>>(dk);

    /* fork: Bg convert + MW2 on side stream, overlapping k_scores */
    cudaEventRecord(evFork, 0);
    cudaStreamWaitEvent(s2, evFork, 0);
    k_prepBg<<<512, 256, 0, s2>>>(gw);
    k_mw2<<<1024, 1024, 0, s2>>>(dk, gw);
    cudaEventRecord(evJoin, s2);

    /* main stream: scores (DRAM-bound, hides the side-stream work) */
    k_scores<<<ROWS_TOT / 128, 256, SC_SMEM>>>(z);

    /* join before k_gate consumes g_Bg */
    cudaStreamWaitEvent(0, evJoin, 0);
    k_gate<<<(ROWS_TOT / 128) * 8, 512, GATE_SMEM>>>(z, gb, out);
    k_finish<<<1, 448>>>(out, out_size - B_DIM * NDIS);
}